// round 1
// baseline (speedup 1.0000x reference)
#include <cuda_runtime.h>
#include <math.h>

#define DEPTH   12
#define BATCH   16
#define NTOK    256
#define TOKENS  (BATCH*NTOK)     /* 4096 */
#define DIM     768
#define HEADS   12
#define HD      64
#define HIDDEN  2048
#define EPSF    1e-5f

/* ------------------------------------------------------------------ */
/* Scratch (no allocation allowed -> __device__ globals)               */
/* ------------------------------------------------------------------ */
__device__ float g_y[TOKENS*DIM];
__device__ float g_q[TOKENS*DIM];
__device__ float g_k[TOKENS*DIM];
__device__ float g_v[TOKENS*DIM];
__device__ float g_o[TOKENS*DIM];
__device__ float g_g[TOKENS*HIDDEN];
__device__ float g_u[TOKENS*HIDDEN];
__device__ float g_m[TOKENS*HIDDEN];

/* ------------------------------------------------------------------ */
/* h = x + pos (pos broadcast over batch)                              */
/* ------------------------------------------------------------------ */
__global__ void add_pos_kernel(const float* __restrict__ x,
                               const float* __restrict__ pos,
                               float* __restrict__ h) {
    int idx = blockIdx.x * blockDim.x + threadIdx.x;
    if (idx < TOKENS*DIM) h[idx] = x[idx] + pos[idx % (NTOK*DIM)];
}

/* ------------------------------------------------------------------ */
/* Block reduction helper (blockDim.x == 256)                          */
/* ------------------------------------------------------------------ */
__device__ __forceinline__ float2 block_reduce_2(float s, float s2) {
    __shared__ float red[16];
    #pragma unroll
    for (int o = 16; o > 0; o >>= 1) {
        s  += __shfl_down_sync(0xffffffffu, s,  o);
        s2 += __shfl_down_sync(0xffffffffu, s2, o);
    }
    int w = threadIdx.x >> 5, l = threadIdx.x & 31;
    if (l == 0) { red[w] = s; red[8 + w] = s2; }
    __syncthreads();
    if (threadIdx.x < 32) {
        s  = (l < 8) ? red[l]     : 0.f;
        s2 = (l < 8) ? red[8 + l] : 0.f;
        #pragma unroll
        for (int o = 4; o > 0; o >>= 1) {
            s  += __shfl_down_sync(0xffffffffu, s,  o);
            s2 += __shfl_down_sync(0xffffffffu, s2, o);
        }
        if (l == 0) { red[0] = s; red[1] = s2; }
    }
    __syncthreads();
    return make_float2(red[0], red[1]);
}

/* ------------------------------------------------------------------ */
/* LayerNorm: one block per token, C = DIM (768)                       */
/* ------------------------------------------------------------------ */
__global__ void __launch_bounds__(256) ln_kernel(
    const float* __restrict__ x, const float* __restrict__ w,
    const float* __restrict__ b, float* __restrict__ out, int C) {
    int t = blockIdx.x;
    const float* xr = x + (size_t)t * C;
    float s = 0.f, s2 = 0.f;
    for (int c = threadIdx.x; c < C; c += 256) {
        float v = xr[c];
        s += v; s2 += v * v;
    }
    float2 r = block_reduce_2(s, s2);
    float mean = r.x / C;
    float var  = r.y / C - mean * mean;
    float inv  = rsqrtf(var + EPSF);
    float* orow = out + (size_t)t * C;
    for (int c = threadIdx.x; c < C; c += 256)
        orow[c] = (xr[c] - mean) * inv * w[c] + b[c];
}

/* ------------------------------------------------------------------ */
/* silu(g)*u then LayerNorm over HIDDEN. One block per token.          */
/* ------------------------------------------------------------------ */
__global__ void __launch_bounds__(256) mlp_act_ln_kernel(
    const float* __restrict__ g, const float* __restrict__ u,
    const float* __restrict__ w, const float* __restrict__ b,
    float* __restrict__ out) {
    int t = blockIdx.x;
    __shared__ float buf[HIDDEN];
    const float* gr = g + (size_t)t * HIDDEN;
    const float* ur = u + (size_t)t * HIDDEN;
    float s = 0.f, s2 = 0.f;
    for (int c = threadIdx.x; c < HIDDEN; c += 256) {
        float gv = gr[c];
        float a  = gv / (1.f + __expf(-gv)) * ur[c];
        buf[c] = a;
        s += a; s2 += a * a;
    }
    __syncthreads();          /* buf fully written before reduce reuse */
    float2 r = block_reduce_2(s, s2);
    float mean = r.x / HIDDEN;
    float var  = r.y / HIDDEN - mean * mean;
    float inv  = rsqrtf(var + EPSF);
    float* orow = out + (size_t)t * HIDDEN;
    for (int c = threadIdx.x; c < HIDDEN; c += 256)
        orow[c] = (buf[c] - mean) * inv * w[c] + b[c];
}

/* ------------------------------------------------------------------ */
/* SGEMM (NT): C[m,n] = sum_k A[m,k]*B[n,k] (+bias[n]) (+res[m,n])     */
/* 128x128 tile, BK=8, 256 threads, 8x8 register tile per thread.      */
/* M,Nn multiples of 128; K multiple of 8.                             */
/* ------------------------------------------------------------------ */
__global__ void __launch_bounds__(256) gemm_nt(
    const float* __restrict__ A, const float* __restrict__ Bw,
    const float* __restrict__ bias, const float* __restrict__ res,
    float* __restrict__ C, int M, int Nn, int K) {
    __shared__ __align__(16) float As[8][132];
    __shared__ __align__(16) float Bs[8][132];
    int bm = blockIdx.y * 128, bn = blockIdx.x * 128;
    int tid = threadIdx.x;
    int tx = tid & 15, ty = tid >> 4;

    float acc[8][8];
    #pragma unroll
    for (int i = 0; i < 8; i++)
        #pragma unroll
        for (int j = 0; j < 8; j++) acc[i][j] = 0.f;

    int lm = tid >> 1;           /* row within tile 0..127 */
    int lk = (tid & 1) * 4;      /* k offset 0 or 4        */
    const float* Ag = A  + (size_t)(bm + lm) * K + lk;
    const float* Bg = Bw + (size_t)(bn + lm) * K + lk;

    for (int k0 = 0; k0 < K; k0 += 8) {
        float4 av = *(const float4*)(Ag + k0);
        float4 bv = *(const float4*)(Bg + k0);
        As[lk+0][lm] = av.x; As[lk+1][lm] = av.y;
        As[lk+2][lm] = av.z; As[lk+3][lm] = av.w;
        Bs[lk+0][lm] = bv.x; Bs[lk+1][lm] = bv.y;
        Bs[lk+2][lm] = bv.z; Bs[lk+3][lm] = bv.w;
        __syncthreads();
        #pragma unroll
        for (int kk = 0; kk < 8; kk++) {
            float a[8], b[8];
            *(float4*)(a)     = *(const float4*)&As[kk][ty*8];
            *(float4*)(a + 4) = *(const float4*)&As[kk][ty*8 + 4];
            *(float4*)(b)     = *(const float4*)&Bs[kk][tx*8];
            *(float4*)(b + 4) = *(const float4*)&Bs[kk][tx*8 + 4];
            #pragma unroll
            for (int i = 0; i < 8; i++)
                #pragma unroll
                for (int j = 0; j < 8; j++)
                    acc[i][j] += a[i] * b[j];
        }
        __syncthreads();
    }

    #pragma unroll
    for (int i = 0; i < 8; i++) {
        int m = bm + ty*8 + i;
        #pragma unroll
        for (int j = 0; j < 8; j++) {
            int n = bn + tx*8 + j;
            float v = acc[i][j];
            if (bias) v += bias[n];
            if (res)  v += res[(size_t)m * Nn + n];
            C[(size_t)m * Nn + n] = v;
        }
    }
}

/* ------------------------------------------------------------------ */
/* RoPE on q and k in place. One thread per (even,odd) pair.           */
/* emb[n, 0:64]=sin, emb[n, 64:128]=cos                                */
/* ------------------------------------------------------------------ */
__global__ void rope_kernel(float* __restrict__ q, float* __restrict__ k,
                            const float* __restrict__ emb) {
    int p = blockIdx.x * blockDim.x + threadIdx.x;   /* pair index */
    if (p >= TOKENS * (DIM/2)) return;
    int t  = p / (DIM/2);
    int c0 = (p % (DIM/2)) * 2;          /* even channel, pair within head */
    int n  = t % NTOK;
    int d  = c0 % HD;                    /* even head-dim index */
    const float* e = emb + n * (2*HD);
    float s0 = e[d],      s1 = e[d+1];
    float c0v = e[HD+d],  c1v = e[HD+d+1];
    size_t i0 = (size_t)t * DIM + c0;
    float q0 = q[i0], q1 = q[i0+1];
    q[i0]   = q0 * c0v - q1 * s0;
    q[i0+1] = q1 * c1v + q0 * s1;
    float k0 = k[i0], k1 = k[i0+1];
    k[i0]   = k0 * c0v - k1 * s0;
    k[i0+1] = k1 * c1v + k0 * s1;
}

/* ------------------------------------------------------------------ */
/* Attention: one block per (batch, head). K,V tiles in shared memory. */
/* 256 threads, one query row per thread, online softmax.              */
/* ------------------------------------------------------------------ */
__global__ void __launch_bounds__(256) attn_kernel(
    const float* __restrict__ q, const float* __restrict__ k,
    const float* __restrict__ v, float* __restrict__ o) {
    extern __shared__ float sm[];
    float* Ks = sm;                 /* [256][64] */
    float* Vs = sm + NTOK * HD;     /* [256][64] */
    int bh = blockIdx.x;
    int b  = bh / HEADS, h = bh % HEADS;
    size_t base = (size_t)(b * NTOK) * DIM + h * HD;
    int tid = threadIdx.x;

    for (int idx = tid; idx < NTOK * HD; idx += 256) {
        int row = idx >> 6, col = idx & 63;
        Ks[idx] = k[base + (size_t)row * DIM + col];
        Vs[idx] = v[base + (size_t)row * DIM + col];
    }
    __syncthreads();

    const float scale = 0.125f;     /* 1/sqrt(64) */
    int i = tid;                    /* query row  */
    float qreg[HD];
    #pragma unroll
    for (int d = 0; d < HD; d++)
        qreg[d] = q[base + (size_t)i * DIM + d] * scale;

    float mrun = -1e30f, lrun = 0.f;
    float accv[HD];
    #pragma unroll
    for (int d = 0; d < HD; d++) accv[d] = 0.f;

    for (int j = 0; j < NTOK; j++) {
        float s = 0.f;
        const float* kr = Ks + j * HD;
        #pragma unroll
        for (int d = 0; d < HD; d++) s += qreg[d] * kr[d];
        float mnew = fmaxf(mrun, s);
        float c = __expf(mrun - mnew);
        float p = __expf(s - mnew);
        lrun = lrun * c + p;
        const float* vr = Vs + j * HD;
        #pragma unroll
        for (int d = 0; d < HD; d++) accv[d] = accv[d] * c + p * vr[d];
        mrun = mnew;
    }
    float inv = 1.f / lrun;
    #pragma unroll
    for (int d = 0; d < HD; d++)
        o[base + (size_t)i * DIM + d] = accv[d] * inv;
}

/* ------------------------------------------------------------------ */
/* Launch                                                              */
/* ------------------------------------------------------------------ */
extern "C" void kernel_launch(void* const* d_in, const int* in_sizes, int n_in,
                              void* d_out, int out_size) {
    const float* x      = (const float*)d_in[0];
    const float* pos    = (const float*)d_in[1];
    const float* rope   = (const float*)d_in[2];
    const float* ln1_w  = (const float*)d_in[3];
    const float* ln1_b  = (const float*)d_in[4];
    const float* wq     = (const float*)d_in[5];
    const float* bq     = (const float*)d_in[6];
    const float* wk     = (const float*)d_in[7];
    const float* wv     = (const float*)d_in[8];
    const float* bv     = (const float*)d_in[9];
    const float* wo     = (const float*)d_in[10];
    const float* bo     = (const float*)d_in[11];
    const float* ln2_w  = (const float*)d_in[12];
    const float* ln2_b  = (const float*)d_in[13];
    const float* w1g    = (const float*)d_in[14];
    const float* b1g    = (const float*)d_in[15];
    const float* w1x    = (const float*)d_in[16];
    const float* b1x    = (const float*)d_in[17];
    const float* lnm_w  = (const float*)d_in[18];
    const float* lnm_b  = (const float*)d_in[19];
    const float* w2     = (const float*)d_in[20];
    const float* b2     = (const float*)d_in[21];
    float* h = (float*)d_out;       /* residual stream lives in d_out */

    float *y, *q, *k, *v, *o, *g, *u, *m;
    cudaGetSymbolAddress((void**)&y, g_y);
    cudaGetSymbolAddress((void**)&q, g_q);
    cudaGetSymbolAddress((void**)&k, g_k);
    cudaGetSymbolAddress((void**)&v, g_v);
    cudaGetSymbolAddress((void**)&o, g_o);
    cudaGetSymbolAddress((void**)&g, g_g);
    cudaGetSymbolAddress((void**)&u, g_u);
    cudaGetSymbolAddress((void**)&m, g_m);

    cudaFuncSetAttribute(attn_kernel,
                         cudaFuncAttributeMaxDynamicSharedMemorySize,
                         2 * NTOK * HD * (int)sizeof(float));

    add_pos_kernel<<<(TOKENS*DIM + 255)/256, 256>>>(x, pos, h);

    dim3 gD(DIM/128,    TOKENS/128);   /* 768-wide GEMMs  */
    dim3 gH(HIDDEN/128, TOKENS/128);   /* 2048-wide GEMMs */

    for (int l = 0; l < DEPTH; l++) {
        const float* Wq  = wq  + (size_t)l * DIM * DIM;
        const float* Wk  = wk  + (size_t)l * DIM * DIM;
        const float* Wv  = wv  + (size_t)l * DIM * DIM;
        const float* Wo  = wo  + (size_t)l * DIM * DIM;
        const float* W1g = w1g + (size_t)l * HIDDEN * DIM;
        const float* W1x = w1x + (size_t)l * HIDDEN * DIM;
        const float* W2  = w2  + (size_t)l * DIM * HIDDEN;

        /* ---- attention ---- */
        ln_kernel<<<TOKENS, 256>>>(h, ln1_w + l*DIM, ln1_b + l*DIM, y, DIM);
        gemm_nt<<<gD, 256>>>(y, Wq, bq + l*DIM, nullptr, q, TOKENS, DIM, DIM);
        gemm_nt<<<gD, 256>>>(y, Wk, nullptr,    nullptr, k, TOKENS, DIM, DIM);
        gemm_nt<<<gD, 256>>>(y, Wv, bv + l*DIM, nullptr, v, TOKENS, DIM, DIM);
        rope_kernel<<<(TOKENS*(DIM/2) + 255)/256, 256>>>(q, k, rope);
        attn_kernel<<<BATCH*HEADS, 256, 2*NTOK*HD*sizeof(float)>>>(q, k, v, o);
        gemm_nt<<<gD, 256>>>(o, Wo, bo + l*DIM, h, h, TOKENS, DIM, DIM);

        /* ---- SwiGLU MLP with inner LN ---- */
        ln_kernel<<<TOKENS, 256>>>(h, ln2_w + l*DIM, ln2_b + l*DIM, y, DIM);
        gemm_nt<<<gH, 256>>>(y, W1g, b1g + l*HIDDEN, nullptr, g, TOKENS, HIDDEN, DIM);
        gemm_nt<<<gH, 256>>>(y, W1x, b1x + l*HIDDEN, nullptr, u, TOKENS, HIDDEN, DIM);
        mlp_act_ln_kernel<<<TOKENS, 256>>>(g, u, lnm_w + l*HIDDEN, lnm_b + l*HIDDEN, m);
        gemm_nt<<<gD, 256>>>(m, W2, b2 + l*DIM, h, h, TOKENS, DIM, HIDDEN);
    }
}

// round 4
// speedup vs baseline: 1.8162x; 1.8162x over previous
#include <cuda_runtime.h>
#include <cuda_fp16.h>
#include <math.h>
#include <stdint.h>

#define DEPTH   12
#define BATCH   16
#define NTOK    256
#define TOKENS  (BATCH*NTOK)     /* 4096 */
#define DIM     768
#define HEADS   12
#define HD      64
#define HIDDEN  2048
#define EPSF    1e-5f

/* ------------------------------------------------------------------ */
/* Scratch buffers                                                     */
/* ------------------------------------------------------------------ */
__device__ float  g_q[TOKENS*DIM];
__device__ float  g_k[TOKENS*DIM];
__device__ float  g_v[TOKENS*DIM];
__device__ float  g_g[TOKENS*HIDDEN];
__device__ float  g_u[TOKENS*HIDDEN];
__device__ __half g_yh_hi[TOKENS*DIM];
__device__ __half g_yh_lo[TOKENS*DIM];
__device__ __half g_oh_hi[TOKENS*DIM];
__device__ __half g_oh_lo[TOKENS*DIM];
__device__ __half g_mh_hi[TOKENS*HIDDEN];
__device__ __half g_mh_lo[TOKENS*HIDDEN];

#define WSZ_D   (DEPTH*DIM*DIM)
#define WSZ_H   (DEPTH*HIDDEN*DIM)
#define OFF_WQ  0
#define OFF_WK  (WSZ_D)
#define OFF_WV  (2*WSZ_D)
#define OFF_WO  (3*WSZ_D)
#define OFF_W1G (4*WSZ_D)
#define OFF_W1X (4*WSZ_D + WSZ_H)
#define OFF_W2  (4*WSZ_D + 2*WSZ_H)
#define WTOT    (4*WSZ_D + 3*WSZ_H)
__device__ __half g_wh_hi[WTOT];
__device__ __half g_wh_lo[WTOT];

/* ------------------------------------------------------------------ */
/* PTX helpers (baseline sm_80+ features only)                         */
/* ------------------------------------------------------------------ */
__device__ __forceinline__ uint32_t smem_u32(const void* p) {
    uint32_t a;
    asm("{ .reg .u64 t; cvta.to.shared.u64 t, %1; cvt.u32.u64 %0, t; }"
        : "=r"(a) : "l"(p));
    return a;
}
__device__ __forceinline__ void cp16(uint32_t dst, const void* src) {
    asm volatile("cp.async.cg.shared.global [%0], [%1], 16;"
                 :: "r"(dst), "l"(src) : "memory");
}
__device__ __forceinline__ void cp_commit() {
    asm volatile("cp.async.commit_group;" ::: "memory");
}
__device__ __forceinline__ void cp_wait1() {
    asm volatile("cp.async.wait_group 1;" ::: "memory");
}
__device__ __forceinline__ void cp_wait0() {
    asm volatile("cp.async.wait_group 0;" ::: "memory");
}
__device__ __forceinline__ void ldmx4(uint32_t& r0, uint32_t& r1,
                                      uint32_t& r2, uint32_t& r3, uint32_t a) {
    asm volatile("ldmatrix.sync.aligned.m8n8.x4.shared.b16 {%0,%1,%2,%3}, [%4];"
                 : "=r"(r0), "=r"(r1), "=r"(r2), "=r"(r3) : "r"(a));
}
__device__ __forceinline__ void mma16816(float* c, const uint32_t* a,
                                         uint32_t b0, uint32_t b1) {
    asm volatile(
        "mma.sync.aligned.m16n8k16.row.col.f32.f16.f16.f32 "
        "{%0,%1,%2,%3}, {%4,%5,%6,%7}, {%8,%9}, {%0,%1,%2,%3};"
        : "+f"(c[0]), "+f"(c[1]), "+f"(c[2]), "+f"(c[3])
        : "r"(a[0]), "r"(a[1]), "r"(a[2]), "r"(a[3]), "r"(b0), "r"(b1));
}

/* ------------------------------------------------------------------ */
/* Split-fp16 HMMA GEMM (NT): C = A*B^T (+bias) (+res)                 */
/* A,B given as hi+lo fp16 planes; acc = Ahi*Bhi + Ahi*Blo + Alo*Bhi.  */
/* 128x128 tile, BK=64, double-buffered cp.async.                      */
/* ------------------------------------------------------------------ */
#define PL 16384                       /* plane bytes per buffer */
#define BUFSZ (4*PL)                   /* Ahi|Alo|Bhi|Blo */
#define GEMM_SMEM (2*BUFSZ)            /* 131072 */

__global__ void __launch_bounds__(256) gemm_mma(
    const __half* __restrict__ Ahi, const __half* __restrict__ Alo,
    const __half* __restrict__ Bhi, const __half* __restrict__ Blo,
    const float* __restrict__ bias, const float* __restrict__ res,
    float* __restrict__ C, int M, int N, int K) {
    extern __shared__ __align__(128) char smem[];
    uint32_t sb = smem_u32(smem);
    int tid = threadIdx.x, wid = tid >> 5, lane = tid & 31;
    int wm = wid >> 2, wn = wid & 3;             /* 2 x 4 warp grid */
    int bm = blockIdx.y * 128, bn = blockIdx.x * 128;

    /* ---- cp.async mapping: row = tid>>1, 4 x 16B groups per plane ---- */
    int ld_row = tid >> 1;
    int ld_g0  = (tid & 1) * 4;
    size_t arow_off = (size_t)(bm + ld_row) * K;
    size_t brow_off = (size_t)(bn + ld_row) * K;
    const __half* Agh = Ahi + arow_off;
    const __half* Agl = Alo + arow_off;
    const __half* Bgh = Bhi + brow_off;
    const __half* Bgl = Blo + brow_off;
    uint32_t st_base = (uint32_t)ld_row * 128u;
    int rsw = ld_row & 7;

    /* ---- ldmatrix per-lane bases ---- */
    int l15 = lane & 15, kg = lane >> 4;
    uint32_t arow = (uint32_t)(wm * 64 + l15);
    uint32_t brow = (uint32_t)(wn * 32 + l15);
    int aswz = (int)(arow & 7), bswz = (int)(brow & 7);

    float acc[4][4][4];
    #pragma unroll
    for (int i = 0; i < 4; i++)
        #pragma unroll
        for (int j = 0; j < 4; j++)
            #pragma unroll
            for (int e = 0; e < 4; e++) acc[i][j][e] = 0.f;

    int nch = K >> 6;

    /* prefetch chunk 0 -> buf 0 */
    #pragma unroll
    for (int j = 0; j < 4; j++) {
        int g = ld_g0 + j;
        uint32_t off = st_base + (uint32_t)((g ^ rsw) * 16);
        cp16(sb + off,          Agh + g * 8);
        cp16(sb + PL + off,     Agl + g * 8);
        cp16(sb + 2*PL + off,   Bgh + g * 8);
        cp16(sb + 3*PL + off,   Bgl + g * 8);
    }
    cp_commit();

    for (int c = 0; c < nch; c++) {
        if (c + 1 < nch) {
            uint32_t nb = sb + (uint32_t)(((c + 1) & 1) * BUFSZ);
            int ko = (c + 1) * 64;
            #pragma unroll
            for (int j = 0; j < 4; j++) {
                int g = ld_g0 + j;
                uint32_t off = st_base + (uint32_t)((g ^ rsw) * 16);
                cp16(nb + off,          Agh + ko + g * 8);
                cp16(nb + PL + off,     Agl + ko + g * 8);
                cp16(nb + 2*PL + off,   Bgh + ko + g * 8);
                cp16(nb + 3*PL + off,   Bgl + ko + g * 8);
            }
            cp_commit();
            cp_wait1();
        } else {
            cp_wait0();
        }
        __syncthreads();

        uint32_t ba = sb + (uint32_t)((c & 1) * BUFSZ);
        uint32_t a_hi = ba          + arow * 128u;
        uint32_t a_lo = ba + PL     + arow * 128u;
        uint32_t b_hi = ba + 2*PL   + brow * 128u;
        uint32_t b_lo = ba + 3*PL   + brow * 128u;

        #pragma unroll
        for (int ks = 0; ks < 4; ks++) {
            int g = ks * 2 + kg;
            uint32_t goff = (uint32_t)((g ^ aswz) * 16);
            uint32_t gofb = (uint32_t)((g ^ bswz) * 16);
            uint32_t afh[4][4], afl[4][4], bfh[2][4], bfl[2][4];
            #pragma unroll
            for (int mf = 0; mf < 4; mf++) {
                ldmx4(afh[mf][0], afh[mf][1], afh[mf][2], afh[mf][3],
                      a_hi + (uint32_t)(mf * 2048) + goff);
                ldmx4(afl[mf][0], afl[mf][1], afl[mf][2], afl[mf][3],
                      a_lo + (uint32_t)(mf * 2048) + goff);
            }
            #pragma unroll
            for (int nf2 = 0; nf2 < 2; nf2++) {
                ldmx4(bfh[nf2][0], bfh[nf2][1], bfh[nf2][2], bfh[nf2][3],
                      b_hi + (uint32_t)(nf2 * 2048) + gofb);
                ldmx4(bfl[nf2][0], bfl[nf2][1], bfl[nf2][2], bfl[nf2][3],
                      b_lo + (uint32_t)(nf2 * 2048) + gofb);
            }
            #pragma unroll
            for (int mf = 0; mf < 4; mf++)
                #pragma unroll
                for (int nf = 0; nf < 4; nf++) {
                    uint32_t bh0 = bfh[nf >> 1][nf & 1];
                    uint32_t bh1 = bfh[nf >> 1][(nf & 1) + 2];
                    uint32_t bl0 = bfl[nf >> 1][nf & 1];
                    uint32_t bl1 = bfl[nf >> 1][(nf & 1) + 2];
                    mma16816(acc[mf][nf], afh[mf], bh0, bh1);
                    mma16816(acc[mf][nf], afh[mf], bl0, bl1);
                    mma16816(acc[mf][nf], afl[mf], bh0, bh1);
                }
        }
        __syncthreads();
    }

    /* ---- epilogue: direct register stores (float2) ---- */
    int r0 = lane >> 2, cb = (lane & 3) * 2;
    #pragma unroll
    for (int mf = 0; mf < 4; mf++) {
        #pragma unroll
        for (int nf = 0; nf < 4; nf++) {
            int n0 = bn + wn * 32 + nf * 8 + cb;
            float bz0 = bias ? bias[n0]     : 0.f;
            float bz1 = bias ? bias[n0 + 1] : 0.f;
            #pragma unroll
            for (int half = 0; half < 2; half++) {
                int m0 = bm + wm * 64 + mf * 16 + r0 + half * 8;
                float v0 = acc[mf][nf][half * 2]     + bz0;
                float v1 = acc[mf][nf][half * 2 + 1] + bz1;
                size_t idx = (size_t)m0 * N + n0;
                if (res) { v0 += res[idx]; v1 += res[idx + 1]; }
                *(float2*)(C + idx) = make_float2(v0, v1);
            }
        }
    }
}

/* ------------------------------------------------------------------ */
/* fp32 -> (hi, lo) fp16 split                                         */
/* ------------------------------------------------------------------ */
__device__ __forceinline__ void split2(float a, float b, __half2& h, __half2& l) {
    __half ha = __float2half_rn(a), hb = __float2half_rn(b);
    __half la = __float2half_rn(a - __half2float(ha));
    __half lb = __float2half_rn(b - __half2float(hb));
    h = __halves2half2(ha, hb);
    l = __halves2half2(la, lb);
}
__global__ void cvt_split_kernel(const float* __restrict__ s,
                                 __half* __restrict__ hi,
                                 __half* __restrict__ lo, int n) {
    int i = (blockIdx.x * blockDim.x + threadIdx.x) * 4;
    if (i < n) {
        float4 v = *(const float4*)(s + i);
        __half2 h0, l0, h1, l1;
        split2(v.x, v.y, h0, l0);
        split2(v.z, v.w, h1, l1);
        ((__half2*)(hi + i))[0] = h0; ((__half2*)(hi + i))[1] = h1;
        ((__half2*)(lo + i))[0] = l0; ((__half2*)(lo + i))[1] = l1;
    }
}

/* ------------------------------------------------------------------ */
/* h = x + pos                                                         */
/* ------------------------------------------------------------------ */
__global__ void add_pos_kernel(const float* __restrict__ x,
                               const float* __restrict__ pos,
                               float* __restrict__ h) {
    int idx = blockIdx.x * blockDim.x + threadIdx.x;
    if (idx < TOKENS*DIM) h[idx] = x[idx] + pos[idx % (NTOK*DIM)];
}

/* ------------------------------------------------------------------ */
/* Block reduction                                                     */
/* ------------------------------------------------------------------ */
__device__ __forceinline__ float2 block_reduce_2(float s, float s2) {
    __shared__ float red[16];
    #pragma unroll
    for (int o = 16; o > 0; o >>= 1) {
        s  += __shfl_down_sync(0xffffffffu, s,  o);
        s2 += __shfl_down_sync(0xffffffffu, s2, o);
    }
    int w = threadIdx.x >> 5, l = threadIdx.x & 31;
    if (l == 0) { red[w] = s; red[8 + w] = s2; }
    __syncthreads();
    if (threadIdx.x < 32) {
        s  = (l < 8) ? red[l]     : 0.f;
        s2 = (l < 8) ? red[8 + l] : 0.f;
        #pragma unroll
        for (int o = 4; o > 0; o >>= 1) {
            s  += __shfl_down_sync(0xffffffffu, s,  o);
            s2 += __shfl_down_sync(0xffffffffu, s2, o);
        }
        if (l == 0) { red[0] = s; red[1] = s2; }
    }
    __syncthreads();
    return make_float2(red[0], red[1]);
}

/* ------------------------------------------------------------------ */
/* LayerNorm (fp32 in, split fp16 out)                                 */
/* ------------------------------------------------------------------ */
__global__ void __launch_bounds__(256) ln_kernel(
    const float* __restrict__ x, const float* __restrict__ w,
    const float* __restrict__ b, __half* __restrict__ ohi,
    __half* __restrict__ olo, int C) {
    int t = blockIdx.x;
    const float* xr = x + (size_t)t * C;
    float s = 0.f, s2 = 0.f;
    for (int c = threadIdx.x; c < C; c += 256) {
        float v = xr[c];
        s += v; s2 += v * v;
    }
    float2 r = block_reduce_2(s, s2);
    float mean = r.x / C;
    float var  = r.y / C - mean * mean;
    float inv  = rsqrtf(var + EPSF);
    for (int c = threadIdx.x; c < C; c += 256) {
        float v = (xr[c] - mean) * inv * w[c] + b[c];
        __half h = __float2half_rn(v);
        ohi[(size_t)t * C + c] = h;
        olo[(size_t)t * C + c] = __float2half_rn(v - __half2float(h));
    }
}

/* ------------------------------------------------------------------ */
/* silu(g)*u then LayerNorm over HIDDEN, split fp16 out                */
/* ------------------------------------------------------------------ */
__global__ void __launch_bounds__(256) mlp_act_ln_kernel(
    const float* __restrict__ g, const float* __restrict__ u,
    const float* __restrict__ w, const float* __restrict__ b,
    __half* __restrict__ ohi, __half* __restrict__ olo) {
    int t = blockIdx.x;
    __shared__ float buf[HIDDEN];
    const float* gr = g + (size_t)t * HIDDEN;
    const float* ur = u + (size_t)t * HIDDEN;
    float s = 0.f, s2 = 0.f;
    for (int c = threadIdx.x; c < HIDDEN; c += 256) {
        float gv = gr[c];
        float a  = gv / (1.f + __expf(-gv)) * ur[c];
        buf[c] = a;
        s += a; s2 += a * a;
    }
    __syncthreads();
    float2 r = block_reduce_2(s, s2);
    float mean = r.x / HIDDEN;
    float var  = r.y / HIDDEN - mean * mean;
    float inv  = rsqrtf(var + EPSF);
    for (int c = threadIdx.x; c < HIDDEN; c += 256) {
        float v = (buf[c] - mean) * inv * w[c] + b[c];
        __half h = __float2half_rn(v);
        ohi[(size_t)t * HIDDEN + c] = h;
        olo[(size_t)t * HIDDEN + c] = __float2half_rn(v - __half2float(h));
    }
}

/* ------------------------------------------------------------------ */
/* RoPE on q and k in place                                            */
/* ------------------------------------------------------------------ */
__global__ void rope_kernel(float* __restrict__ q, float* __restrict__ k,
                            const float* __restrict__ emb) {
    int p = blockIdx.x * blockDim.x + threadIdx.x;
    if (p >= TOKENS * (DIM/2)) return;
    int t  = p / (DIM/2);
    int c0 = (p % (DIM/2)) * 2;
    int n  = t % NTOK;
    int d  = c0 % HD;
    const float* e = emb + n * (2*HD);
    float s0 = e[d],      s1 = e[d+1];
    float c0v = e[HD+d],  c1v = e[HD+d+1];
    size_t i0 = (size_t)t * DIM + c0;
    float q0 = q[i0], q1 = q[i0+1];
    q[i0]   = q0 * c0v - q1 * s0;
    q[i0+1] = q1 * c1v + q0 * s1;
    float k0 = k[i0], k1 = k[i0+1];
    k[i0]   = k0 * c0v - k1 * s0;
    k[i0+1] = k1 * c1v + k0 * s1;
}

/* ------------------------------------------------------------------ */
/* Attention (fp32 math, split fp16 output)                            */
/* ------------------------------------------------------------------ */
__global__ void __launch_bounds__(256) attn_kernel(
    const float* __restrict__ q, const float* __restrict__ k,
    const float* __restrict__ v, __half* __restrict__ ohi,
    __half* __restrict__ olo) {
    extern __shared__ float sm[];
    float* Ks = sm;
    float* Vs = sm + NTOK * HD;
    int bh = blockIdx.x;
    int b  = bh / HEADS, h = bh % HEADS;
    size_t base = (size_t)(b * NTOK) * DIM + h * HD;
    int tid = threadIdx.x;

    for (int idx = tid; idx < NTOK * HD; idx += 256) {
        int row = idx >> 6, col = idx & 63;
        Ks[idx] = k[base + (size_t)row * DIM + col];
        Vs[idx] = v[base + (size_t)row * DIM + col];
    }
    __syncthreads();

    const float scale = 0.125f;
    int i = tid;
    float qreg[HD];
    #pragma unroll
    for (int d = 0; d < HD; d++)
        qreg[d] = q[base + (size_t)i * DIM + d] * scale;

    float mrun = -1e30f, lrun = 0.f;
    float accv[HD];
    #pragma unroll
    for (int d = 0; d < HD; d++) accv[d] = 0.f;

    for (int j = 0; j < NTOK; j++) {
        float s = 0.f;
        const float* kr = Ks + j * HD;
        #pragma unroll
        for (int d = 0; d < HD; d++) s += qreg[d] * kr[d];
        float mnew = fmaxf(mrun, s);
        float c = __expf(mrun - mnew);
        float p = __expf(s - mnew);
        lrun = lrun * c + p;
        const float* vr = Vs + j * HD;
        #pragma unroll
        for (int d = 0; d < HD; d++) accv[d] = accv[d] * c + p * vr[d];
        mrun = mnew;
    }
    float inv = 1.f / lrun;
    #pragma unroll
    for (int d = 0; d < HD; d++) {
        float v0 = accv[d] * inv;
        __half hh = __float2half_rn(v0);
        ohi[base + (size_t)i * DIM + d] = hh;
        olo[base + (size_t)i * DIM + d] = __float2half_rn(v0 - __half2float(hh));
    }
}

/* ------------------------------------------------------------------ */
/* Launch                                                              */
/* ------------------------------------------------------------------ */
extern "C" void kernel_launch(void* const* d_in, const int* in_sizes, int n_in,
                              void* d_out, int out_size) {
    const float* x      = (const float*)d_in[0];
    const float* pos    = (const float*)d_in[1];
    const float* rope   = (const float*)d_in[2];
    const float* ln1_w  = (const float*)d_in[3];
    const float* ln1_b  = (const float*)d_in[4];
    const float* wq     = (const float*)d_in[5];
    const float* bq     = (const float*)d_in[6];
    const float* wk     = (const float*)d_in[7];
    const float* wv     = (const float*)d_in[8];
    const float* bv     = (const float*)d_in[9];
    const float* wo     = (const float*)d_in[10];
    const float* bo     = (const float*)d_in[11];
    const float* ln2_w  = (const float*)d_in[12];
    const float* ln2_b  = (const float*)d_in[13];
    const float* w1g    = (const float*)d_in[14];
    const float* b1g    = (const float*)d_in[15];
    const float* w1x    = (const float*)d_in[16];
    const float* b1x    = (const float*)d_in[17];
    const float* lnm_w  = (const float*)d_in[18];
    const float* lnm_b  = (const float*)d_in[19];
    const float* w2     = (const float*)d_in[20];
    const float* b2     = (const float*)d_in[21];
    float* h = (float*)d_out;

    float *q, *k, *v, *g, *u;
    __half *yhh, *yhl, *ohh, *ohl, *mhh, *mhl, *whh, *whl;
    cudaGetSymbolAddress((void**)&q,   g_q);
    cudaGetSymbolAddress((void**)&k,   g_k);
    cudaGetSymbolAddress((void**)&v,   g_v);
    cudaGetSymbolAddress((void**)&g,   g_g);
    cudaGetSymbolAddress((void**)&u,   g_u);
    cudaGetSymbolAddress((void**)&yhh, g_yh_hi);
    cudaGetSymbolAddress((void**)&yhl, g_yh_lo);
    cudaGetSymbolAddress((void**)&ohh, g_oh_hi);
    cudaGetSymbolAddress((void**)&ohl, g_oh_lo);
    cudaGetSymbolAddress((void**)&mhh, g_mh_hi);
    cudaGetSymbolAddress((void**)&mhl, g_mh_lo);
    cudaGetSymbolAddress((void**)&whh, g_wh_hi);
    cudaGetSymbolAddress((void**)&whl, g_wh_lo);

    cudaFuncSetAttribute(gemm_mma, cudaFuncAttributeMaxDynamicSharedMemorySize, GEMM_SMEM);
    cudaFuncSetAttribute(attn_kernel, cudaFuncAttributeMaxDynamicSharedMemorySize,
                         2 * NTOK * HD * (int)sizeof(float));

    /* weight split */
    {
        const int T = 256, V4 = 4 * T;
        cvt_split_kernel<<<(WSZ_D + V4-1)/V4, T>>>(wq,  whh + OFF_WQ,  whl + OFF_WQ,  WSZ_D);
        cvt_split_kernel<<<(WSZ_D + V4-1)/V4, T>>>(wk,  whh + OFF_WK,  whl + OFF_WK,  WSZ_D);
        cvt_split_kernel<<<(WSZ_D + V4-1)/V4, T>>>(wv,  whh + OFF_WV,  whl + OFF_WV,  WSZ_D);
        cvt_split_kernel<<<(WSZ_D + V4-1)/V4, T>>>(wo,  whh + OFF_WO,  whl + OFF_WO,  WSZ_D);
        cvt_split_kernel<<<(WSZ_H + V4-1)/V4, T>>>(w1g, whh + OFF_W1G, whl + OFF_W1G, WSZ_H);
        cvt_split_kernel<<<(WSZ_H + V4-1)/V4, T>>>(w1x, whh + OFF_W1X, whl + OFF_W1X, WSZ_H);
        cvt_split_kernel<<<(WSZ_H + V4-1)/V4, T>>>(w2,  whh + OFF_W2,  whl + OFF_W2,  WSZ_H);
    }

    add_pos_kernel<<<(TOKENS*DIM + 255)/256, 256>>>(x, pos, h);

    dim3 gD(DIM/128,    TOKENS/128);
    dim3 gH(HIDDEN/128, TOKENS/128);

    for (int l = 0; l < DEPTH; l++) {
        size_t od = (size_t)l * DIM * DIM;
        size_t oh2 = (size_t)l * HIDDEN * DIM;

        /* ---- attention ---- */
        ln_kernel<<<TOKENS, 256>>>(h, ln1_w + l*DIM, ln1_b + l*DIM, yhh, yhl, DIM);
        gemm_mma<<<gD, 256, GEMM_SMEM>>>(yhh, yhl, whh + OFF_WQ + od, whl + OFF_WQ + od,
                                         bq + l*DIM, nullptr, q, TOKENS, DIM, DIM);
        gemm_mma<<<gD, 256, GEMM_SMEM>>>(yhh, yhl, whh + OFF_WK + od, whl + OFF_WK + od,
                                         nullptr, nullptr, k, TOKENS, DIM, DIM);
        gemm_mma<<<gD, 256, GEMM_SMEM>>>(yhh, yhl, whh + OFF_WV + od, whl + OFF_WV + od,
                                         bv + l*DIM, nullptr, v, TOKENS, DIM, DIM);
        rope_kernel<<<(TOKENS*(DIM/2) + 255)/256, 256>>>(q, k, rope);
        attn_kernel<<<BATCH*HEADS, 256, 2*NTOK*HD*sizeof(float)>>>(q, k, v, ohh, ohl);
        gemm_mma<<<gD, 256, GEMM_SMEM>>>(ohh, ohl, whh + OFF_WO + od, whl + OFF_WO + od,
                                         bo + l*DIM, h, h, TOKENS, DIM, DIM);

        /* ---- SwiGLU MLP ---- */
        ln_kernel<<<TOKENS, 256>>>(h, ln2_w + l*DIM, ln2_b + l*DIM, yhh, yhl, DIM);
        gemm_mma<<<gH, 256, GEMM_SMEM>>>(yhh, yhl, whh + OFF_W1G + oh2, whl + OFF_W1G + oh2,
                                         b1g + l*HIDDEN, nullptr, g, TOKENS, HIDDEN, DIM);
        gemm_mma<<<gH, 256, GEMM_SMEM>>>(yhh, yhl, whh + OFF_W1X + oh2, whl + OFF_W1X + oh2,
                                         b1x + l*HIDDEN, nullptr, u, TOKENS, HIDDEN, DIM);
        mlp_act_ln_kernel<<<TOKENS, 256>>>(g, u, lnm_w + l*HIDDEN, lnm_b + l*HIDDEN, mhh, mhl);
        gemm_mma<<<gD, 256, GEMM_SMEM>>>(mhh, mhl, whh + OFF_W2 + oh2, whl + OFF_W2 + oh2,
                                         b2 + l*DIM, h, h, TOKENS, DIM, HIDDEN);
    }
}

// round 5
// speedup vs baseline: 2.5591x; 1.4091x over previous
#include <cuda_runtime.h>
#include <cuda_fp16.h>
#include <math.h>
#include <stdint.h>

#define DEPTH   12
#define BATCH   16
#define NTOK    256
#define TOKENS  (BATCH*NTOK)     /* 4096 */
#define DIM     768
#define HEADS   12
#define HD      64
#define HIDDEN  2048
#define EPSF    1e-5f
#define QS      2304             /* packed qkv row stride */
#define GUS     4096             /* packed g|u row stride */

/* ------------------------------------------------------------------ */
/* Scratch buffers                                                     */
/* ------------------------------------------------------------------ */
__device__ float  g_qkv[TOKENS*QS];
__device__ float  g_gu[TOKENS*GUS];
__device__ __half g_yh_hi[TOKENS*DIM];
__device__ __half g_yh_lo[TOKENS*DIM];
__device__ __half g_oh_hi[TOKENS*DIM];
__device__ __half g_oh_lo[TOKENS*DIM];
__device__ __half g_mh_hi[TOKENS*HIDDEN];
__device__ __half g_mh_lo[TOKENS*HIDDEN];

/* packed split weights */
__device__ __half g_wqkv_hi[DEPTH*QS*DIM];
__device__ __half g_wqkv_lo[DEPTH*QS*DIM];
__device__ __half g_wo_hi[DEPTH*DIM*DIM];
__device__ __half g_wo_lo[DEPTH*DIM*DIM];
__device__ __half g_w1_hi[DEPTH*GUS*DIM];
__device__ __half g_w1_lo[DEPTH*GUS*DIM];
__device__ __half g_w2_hi[DEPTH*DIM*HIDDEN];
__device__ __half g_w2_lo[DEPTH*DIM*HIDDEN];
__device__ float  g_bqkv[DEPTH*QS];
__device__ float  g_b1[DEPTH*GUS];

/* ------------------------------------------------------------------ */
/* PTX helpers (baseline sm_80+ only)                                  */
/* ------------------------------------------------------------------ */
__device__ __forceinline__ uint32_t smem_u32(const void* p) {
    uint32_t a;
    asm("{ .reg .u64 t; cvta.to.shared.u64 t, %1; cvt.u32.u64 %0, t; }"
        : "=r"(a) : "l"(p));
    return a;
}
__device__ __forceinline__ void cp16(uint32_t dst, const void* src) {
    asm volatile("cp.async.cg.shared.global [%0], [%1], 16;"
                 :: "r"(dst), "l"(src) : "memory");
}
__device__ __forceinline__ void cp_commit() {
    asm volatile("cp.async.commit_group;" ::: "memory");
}
__device__ __forceinline__ void cp_wait1() {
    asm volatile("cp.async.wait_group 1;" ::: "memory");
}
__device__ __forceinline__ void cp_wait0() {
    asm volatile("cp.async.wait_group 0;" ::: "memory");
}
__device__ __forceinline__ void ldmx4(uint32_t& r0, uint32_t& r1,
                                      uint32_t& r2, uint32_t& r3, uint32_t a) {
    asm volatile("ldmatrix.sync.aligned.m8n8.x4.shared.b16 {%0,%1,%2,%3}, [%4];"
                 : "=r"(r0), "=r"(r1), "=r"(r2), "=r"(r3) : "r"(a));
}
__device__ __forceinline__ void mma16816(float* c, const uint32_t* a,
                                         uint32_t b0, uint32_t b1) {
    /* no volatile: let the scheduler interleave independent MMAs */
    asm("mma.sync.aligned.m16n8k16.row.col.f32.f16.f16.f32 "
        "{%0,%1,%2,%3}, {%4,%5,%6,%7}, {%8,%9}, {%0,%1,%2,%3};"
        : "+f"(c[0]), "+f"(c[1]), "+f"(c[2]), "+f"(c[3])
        : "r"(a[0]), "r"(a[1]), "r"(a[2]), "r"(a[3]), "r"(b0), "r"(b1));
}

/* ------------------------------------------------------------------ */
/* Split-fp16 HMMA GEMM (NT), templated on BN.                         */
/* C = Ahi*Bhi + Ahi*Blo + Alo*Bhi (+bias) (+res)                      */
/* BM=128, BK=64, double-buffered cp.async, threads = 2*BN.            */
/* ------------------------------------------------------------------ */
template<int BN>
__global__ void __launch_bounds__(2*BN, 1) gemm_mma(
    const __half* __restrict__ Ahi, const __half* __restrict__ Alo,
    const __half* __restrict__ Bhi, const __half* __restrict__ Blo,
    const float* __restrict__ bias, const float* __restrict__ res,
    float* __restrict__ C, int M, int N, int K) {
    constexpr int T  = 2*BN;          /* threads */
    constexpr int WN = BN/32;         /* warps along N */
    constexpr int PA = 16384;         /* A plane bytes (128 rows x 128B) */
    constexpr int PB = BN*128;        /* B plane bytes */
    constexpr int BUFSZ = 2*PA + 2*PB;
    constexpr int CA = 1024/T;        /* A 16B-chunks per thread per plane */
    constexpr int CB = 4;             /* B chunks per thread per plane */
    extern __shared__ __align__(128) char smem[];
    uint32_t sb = smem_u32(smem);
    int tid = threadIdx.x, wid = tid >> 5, lane = tid & 31;
    int wm = wid / WN, wn = wid % WN;
    int bm = blockIdx.y * 128, bn = blockIdx.x * BN;

    /* ---- ldmatrix per-lane bases ---- */
    int l15 = lane & 15, kg = lane >> 4;
    uint32_t arow = (uint32_t)(wm * 64 + l15);
    uint32_t brow = (uint32_t)(wn * 32 + l15);
    int aswz = (int)(arow & 7), bswz = (int)(brow & 7);

    float acc[4][4][4];
    #pragma unroll
    for (int i = 0; i < 4; i++)
        #pragma unroll
        for (int j = 0; j < 4; j++)
            #pragma unroll
            for (int e = 0; e < 4; e++) acc[i][j][e] = 0.f;

    int nch = K >> 6;

    auto load_chunk = [&](uint32_t dst, int ko) {
        #pragma unroll
        for (int j = 0; j < CA; j++) {
            int id = tid + j * T;
            int row = id >> 3, g = id & 7;
            uint32_t off = (uint32_t)row * 128u + (uint32_t)((g ^ (row & 7)) * 16);
            size_t so = (size_t)(bm + row) * K + ko + g * 8;
            cp16(dst + off,      Ahi + so);
            cp16(dst + PA + off, Alo + so);
        }
        #pragma unroll
        for (int j = 0; j < CB; j++) {
            int id = tid + j * T;
            int row = id >> 3, g = id & 7;
            uint32_t off = (uint32_t)row * 128u + (uint32_t)((g ^ (row & 7)) * 16);
            size_t so = (size_t)(bn + row) * K + ko + g * 8;
            cp16(dst + 2*PA + off,      Bhi + so);
            cp16(dst + 2*PA + PB + off, Blo + so);
        }
    };

    load_chunk(sb, 0);
    cp_commit();

    for (int c = 0; c < nch; c++) {
        if (c + 1 < nch) {
            load_chunk(sb + (uint32_t)(((c + 1) & 1) * BUFSZ), (c + 1) * 64);
            cp_commit();
            cp_wait1();
        } else {
            cp_wait0();
        }
        __syncthreads();

        uint32_t ba = sb + (uint32_t)((c & 1) * BUFSZ);
        uint32_t a_hi = ba          + arow * 128u;
        uint32_t a_lo = ba + PA     + arow * 128u;
        uint32_t b_hi = ba + 2*PA   + brow * 128u;
        uint32_t b_lo = ba + 2*PA + PB + brow * 128u;

        #pragma unroll
        for (int ks = 0; ks < 4; ks++) {
            int g = ks * 2 + kg;
            uint32_t goff = (uint32_t)((g ^ aswz) * 16);
            uint32_t gofb = (uint32_t)((g ^ bswz) * 16);
            uint32_t afh[4][4], afl[4][4], bfh[2][4], bfl[2][4];
            #pragma unroll
            for (int mf = 0; mf < 4; mf++) {
                ldmx4(afh[mf][0], afh[mf][1], afh[mf][2], afh[mf][3],
                      a_hi + (uint32_t)(mf * 2048) + goff);
                ldmx4(afl[mf][0], afl[mf][1], afl[mf][2], afl[mf][3],
                      a_lo + (uint32_t)(mf * 2048) + goff);
            }
            #pragma unroll
            for (int nf2 = 0; nf2 < 2; nf2++) {
                ldmx4(bfh[nf2][0], bfh[nf2][1], bfh[nf2][2], bfh[nf2][3],
                      b_hi + (uint32_t)(nf2 * 2048) + gofb);
                ldmx4(bfl[nf2][0], bfl[nf2][1], bfl[nf2][2], bfl[nf2][3],
                      b_lo + (uint32_t)(nf2 * 2048) + gofb);
            }
            /* term-outer: 16 independent accs between reuse of an acc */
            #pragma unroll
            for (int mf = 0; mf < 4; mf++)
                #pragma unroll
                for (int nf = 0; nf < 4; nf++)
                    mma16816(acc[mf][nf], afh[mf],
                             bfh[nf >> 1][nf & 1], bfh[nf >> 1][(nf & 1) + 2]);
            #pragma unroll
            for (int mf = 0; mf < 4; mf++)
                #pragma unroll
                for (int nf = 0; nf < 4; nf++)
                    mma16816(acc[mf][nf], afh[mf],
                             bfl[nf >> 1][nf & 1], bfl[nf >> 1][(nf & 1) + 2]);
            #pragma unroll
            for (int mf = 0; mf < 4; mf++)
                #pragma unroll
                for (int nf = 0; nf < 4; nf++)
                    mma16816(acc[mf][nf], afl[mf],
                             bfh[nf >> 1][nf & 1], bfh[nf >> 1][(nf & 1) + 2]);
        }
        __syncthreads();
    }

    /* ---- epilogue ---- */
    int r0 = lane >> 2, cb = (lane & 3) * 2;
    #pragma unroll
    for (int mf = 0; mf < 4; mf++) {
        #pragma unroll
        for (int nf = 0; nf < 4; nf++) {
            int n0 = bn + wn * 32 + nf * 8 + cb;
            float bz0 = bias ? bias[n0]     : 0.f;
            float bz1 = bias ? bias[n0 + 1] : 0.f;
            #pragma unroll
            for (int half = 0; half < 2; half++) {
                int m0 = bm + wm * 64 + mf * 16 + r0 + half * 8;
                float v0 = acc[mf][nf][half * 2]     + bz0;
                float v1 = acc[mf][nf][half * 2 + 1] + bz1;
                size_t idx = (size_t)m0 * N + n0;
                if (res) { v0 += res[idx]; v1 += res[idx + 1]; }
                *(float2*)(C + idx) = make_float2(v0, v1);
            }
        }
    }
}

/* ------------------------------------------------------------------ */
/* fp32 -> (hi, lo) split, with per-layer row repacking                */
/* src layout [DEPTH][R][768], dst layout [DEPTH][ROWT][K] row rowoff  */
/* ------------------------------------------------------------------ */
__device__ __forceinline__ void split2(float a, float b, __half2& h, __half2& l) {
    __half ha = __float2half_rn(a), hb = __float2half_rn(b);
    __half la = __float2half_rn(a - __half2float(ha));
    __half lb = __float2half_rn(b - __half2float(hb));
    h = __halves2half2(ha, hb);
    l = __halves2half2(la, lb);
}
__global__ void cvt_split_pack(const float* __restrict__ s,
                               __half* __restrict__ hi, __half* __restrict__ lo,
                               int n, int lr /* R*K */, int ltot /* ROWT*K */,
                               int rowoff_elems) {
    int i = (blockIdx.x * blockDim.x + threadIdx.x) * 4;
    if (i >= n) return;
    int l = i / lr;
    int rem = i - l * lr;
    size_t d = (size_t)l * ltot + rowoff_elems + rem;
    float4 v = *(const float4*)(s + i);
    __half2 h0, l0, h1, l1;
    split2(v.x, v.y, h0, l0);
    split2(v.z, v.w, h1, l1);
    ((__half2*)(hi + d))[0] = h0; ((__half2*)(hi + d))[1] = h1;
    ((__half2*)(lo + d))[0] = l0; ((__half2*)(lo + d))[1] = l1;
}

__global__ void pack_bias_qkv(const float* __restrict__ bq,
                              const float* __restrict__ bv,
                              float* __restrict__ dst) {
    int i = blockIdx.x * blockDim.x + threadIdx.x;
    if (i >= DEPTH*QS) return;
    int l = i / QS, c = i % QS;
    dst[i] = c < DIM ? bq[l*DIM + c]
           : (c < 2*DIM ? 0.f : bv[l*DIM + c - 2*DIM]);
}
__global__ void pack_bias_mlp(const float* __restrict__ bg,
                              const float* __restrict__ bx,
                              float* __restrict__ dst) {
    int i = blockIdx.x * blockDim.x + threadIdx.x;
    if (i >= DEPTH*GUS) return;
    int l = i / GUS, c = i % GUS;
    dst[i] = c < HIDDEN ? bg[l*HIDDEN + c] : bx[l*HIDDEN + c - HIDDEN];
}

/* ------------------------------------------------------------------ */
/* h = x + pos                                                         */
/* ------------------------------------------------------------------ */
__global__ void add_pos_kernel(const float* __restrict__ x,
                               const float* __restrict__ pos,
                               float* __restrict__ h) {
    int idx = blockIdx.x * blockDim.x + threadIdx.x;
    if (idx < TOKENS*DIM) h[idx] = x[idx] + pos[idx % (NTOK*DIM)];
}

/* ------------------------------------------------------------------ */
/* Block reduction                                                     */
/* ------------------------------------------------------------------ */
__device__ __forceinline__ float2 block_reduce_2(float s, float s2) {
    __shared__ float red[16];
    #pragma unroll
    for (int o = 16; o > 0; o >>= 1) {
        s  += __shfl_down_sync(0xffffffffu, s,  o);
        s2 += __shfl_down_sync(0xffffffffu, s2, o);
    }
    int w = threadIdx.x >> 5, l = threadIdx.x & 31;
    if (l == 0) { red[w] = s; red[8 + w] = s2; }
    __syncthreads();
    if (threadIdx.x < 32) {
        s  = (l < 8) ? red[l]     : 0.f;
        s2 = (l < 8) ? red[8 + l] : 0.f;
        #pragma unroll
        for (int o = 4; o > 0; o >>= 1) {
            s  += __shfl_down_sync(0xffffffffu, s,  o);
            s2 += __shfl_down_sync(0xffffffffu, s2, o);
        }
        if (l == 0) { red[0] = s; red[1] = s2; }
    }
    __syncthreads();
    return make_float2(red[0], red[1]);
}

/* ------------------------------------------------------------------ */
/* LayerNorm (fp32 in, split fp16 out)                                 */
/* ------------------------------------------------------------------ */
__global__ void __launch_bounds__(256) ln_kernel(
    const float* __restrict__ x, const float* __restrict__ w,
    const float* __restrict__ b, __half* __restrict__ ohi,
    __half* __restrict__ olo, int C) {
    int t = blockIdx.x;
    const float* xr = x + (size_t)t * C;
    float s = 0.f, s2 = 0.f;
    for (int c = threadIdx.x; c < C; c += 256) {
        float v = xr[c];
        s += v; s2 += v * v;
    }
    float2 r = block_reduce_2(s, s2);
    float mean = r.x / C;
    float var  = r.y / C - mean * mean;
    float inv  = rsqrtf(var + EPSF);
    for (int c = threadIdx.x; c < C; c += 256) {
        float v = (xr[c] - mean) * inv * w[c] + b[c];
        __half h = __float2half_rn(v);
        ohi[(size_t)t * C + c] = h;
        olo[(size_t)t * C + c] = __float2half_rn(v - __half2float(h));
    }
}

/* ------------------------------------------------------------------ */
/* silu(g)*u then LN over HIDDEN; g|u packed row stride GUS            */
/* ------------------------------------------------------------------ */
__global__ void __launch_bounds__(256) mlp_act_ln_kernel(
    const float* __restrict__ gu,
    const float* __restrict__ w, const float* __restrict__ b,
    __half* __restrict__ ohi, __half* __restrict__ olo) {
    int t = blockIdx.x;
    __shared__ float buf[HIDDEN];
    const float* gr = gu + (size_t)t * GUS;
    const float* ur = gr + HIDDEN;
    float s = 0.f, s2 = 0.f;
    for (int c = threadIdx.x; c < HIDDEN; c += 256) {
        float gv = gr[c];
        float a  = gv / (1.f + __expf(-gv)) * ur[c];
        buf[c] = a;
        s += a; s2 += a * a;
    }
    __syncthreads();
    float2 r = block_reduce_2(s, s2);
    float mean = r.x / HIDDEN;
    float var  = r.y / HIDDEN - mean * mean;
    float inv  = rsqrtf(var + EPSF);
    for (int c = threadIdx.x; c < HIDDEN; c += 256) {
        float v = (buf[c] - mean) * inv * w[c] + b[c];
        __half h = __float2half_rn(v);
        ohi[(size_t)t * HIDDEN + c] = h;
        olo[(size_t)t * HIDDEN + c] = __float2half_rn(v - __half2float(h));
    }
}

/* ------------------------------------------------------------------ */
/* RoPE in place on packed qkv (q cols 0..767, k cols 768..1535)       */
/* ------------------------------------------------------------------ */
__global__ void rope_kernel(float* __restrict__ qkv, const float* __restrict__ emb) {
    int p = blockIdx.x * blockDim.x + threadIdx.x;
    if (p >= TOKENS * (DIM/2)) return;
    int t  = p / (DIM/2);
    int c0 = (p % (DIM/2)) * 2;
    int n  = t % NTOK;
    int d  = c0 % HD;
    const float* e = emb + n * (2*HD);
    float s0 = e[d],      s1 = e[d+1];
    float c0v = e[HD+d],  c1v = e[HD+d+1];
    size_t i0 = (size_t)t * QS + c0;
    float q0 = qkv[i0], q1 = qkv[i0+1];
    qkv[i0]   = q0 * c0v - q1 * s0;
    qkv[i0+1] = q1 * c1v + q0 * s1;
    size_t k0i = i0 + DIM;
    float k0 = qkv[k0i], k1 = qkv[k0i+1];
    qkv[k0i]   = k0 * c0v - k1 * s0;
    qkv[k0i+1] = k1 * c1v + k0 * s1;
}

/* ------------------------------------------------------------------ */
/* Attention: 2 lanes per query row (32-dim slices), KV tiled x128.    */
/* grid = BATCH*HEADS*2, 256 threads, 64KB smem -> 2 CTAs/SM.          */
/* ------------------------------------------------------------------ */
#define KVT 128
__global__ void __launch_bounds__(256) attn_kernel(
    const float* __restrict__ qkv, __half* __restrict__ ohi,
    __half* __restrict__ olo) {
    extern __shared__ float sm[];
    float* Ks = sm;               /* [KVT][64] */
    float* Vs = sm + KVT * HD;    /* [KVT][64] */
    int blk = blockIdx.x;
    int half_blk = blk & 1;
    int bh = blk >> 1;
    int b  = bh / HEADS, h = bh % HEADS;
    size_t base_q = (size_t)(b * NTOK) * QS + h * HD;
    int tid = threadIdx.x, lane = tid & 31, wid = tid >> 5;
    int row_local = wid * 16 + (lane & 15);   /* 0..127 */
    int part = lane >> 4;                     /* 0/1 -> dim slice */
    int i = half_blk * 128 + row_local;       /* query row 0..255 */

    const float scale = 0.125f;
    float qreg[32];
    {
        const float* qp = qkv + base_q + (size_t)i * QS + part * 32;
        #pragma unroll
        for (int d = 0; d < 32; d++) qreg[d] = qp[d] * scale;
    }

    float mrun = -1e30f, lrun = 0.f;
    float accv[32];
    #pragma unroll
    for (int d = 0; d < 32; d++) accv[d] = 0.f;

    for (int tkv = 0; tkv < NTOK / KVT; tkv++) {
        for (int idx = tid; idx < KVT * HD; idx += 256) {
            int row = idx >> 6, col = idx & 63;
            size_t src = base_q + (size_t)(tkv * KVT + row) * QS + col;
            Ks[idx] = qkv[src + DIM];
            Vs[idx] = qkv[src + 2*DIM];
        }
        __syncthreads();

        for (int j = 0; j < KVT; j++) {
            const float* kr = Ks + j * HD + part * 32;
            float s = 0.f;
            #pragma unroll
            for (int d = 0; d < 32; d++) s += qreg[d] * kr[d];
            s += __shfl_xor_sync(0xffffffffu, s, 16);
            float mnew = fmaxf(mrun, s);
            float cc = __expf(mrun - mnew);
            float p  = __expf(s - mnew);
            lrun = lrun * cc + p;
            const float* vr = Vs + j * HD + part * 32;
            #pragma unroll
            for (int d = 0; d < 32; d++) accv[d] = accv[d] * cc + p * vr[d];
            mrun = mnew;
        }
        __syncthreads();
    }

    float inv = 1.f / lrun;
    size_t ob = (size_t)(b * NTOK + i) * DIM + h * HD + part * 32;
    #pragma unroll
    for (int d = 0; d < 32; d++) {
        float v0 = accv[d] * inv;
        __half hh = __float2half_rn(v0);
        ohi[ob + d] = hh;
        olo[ob + d] = __float2half_rn(v0 - __half2float(hh));
    }
}

/* ------------------------------------------------------------------ */
/* Launch                                                              */
/* ------------------------------------------------------------------ */
extern "C" void kernel_launch(void* const* d_in, const int* in_sizes, int n_in,
                              void* d_out, int out_size) {
    const float* x      = (const float*)d_in[0];
    const float* pos    = (const float*)d_in[1];
    const float* rope   = (const float*)d_in[2];
    const float* ln1_w  = (const float*)d_in[3];
    const float* ln1_b  = (const float*)d_in[4];
    const float* wq     = (const float*)d_in[5];
    const float* bq     = (const float*)d_in[6];
    const float* wk     = (const float*)d_in[7];
    const float* wv     = (const float*)d_in[8];
    const float* bv     = (const float*)d_in[9];
    const float* wo     = (const float*)d_in[10];
    const float* bo     = (const float*)d_in[11];
    const float* ln2_w  = (const float*)d_in[12];
    const float* ln2_b  = (const float*)d_in[13];
    const float* w1g    = (const float*)d_in[14];
    const float* b1g    = (const float*)d_in[15];
    const float* w1x    = (const float*)d_in[16];
    const float* b1x    = (const float*)d_in[17];
    const float* lnm_w  = (const float*)d_in[18];
    const float* lnm_b  = (const float*)d_in[19];
    const float* w2     = (const float*)d_in[20];
    const float* b2     = (const float*)d_in[21];
    float* h = (float*)d_out;

    float *qkv, *gu, *bqkv, *b1;
    __half *yhh, *yhl, *ohh, *ohl, *mhh, *mhl;
    __half *wqkvh, *wqkvl, *woh, *wol, *w1h, *w1l, *w2h, *w2l;
    cudaGetSymbolAddress((void**)&qkv,   g_qkv);
    cudaGetSymbolAddress((void**)&gu,    g_gu);
    cudaGetSymbolAddress((void**)&bqkv,  g_bqkv);
    cudaGetSymbolAddress((void**)&b1,    g_b1);
    cudaGetSymbolAddress((void**)&yhh,   g_yh_hi);
    cudaGetSymbolAddress((void**)&yhl,   g_yh_lo);
    cudaGetSymbolAddress((void**)&ohh,   g_oh_hi);
    cudaGetSymbolAddress((void**)&ohl,   g_oh_lo);
    cudaGetSymbolAddress((void**)&mhh,   g_mh_hi);
    cudaGetSymbolAddress((void**)&mhl,   g_mh_lo);
    cudaGetSymbolAddress((void**)&wqkvh, g_wqkv_hi);
    cudaGetSymbolAddress((void**)&wqkvl, g_wqkv_lo);
    cudaGetSymbolAddress((void**)&woh,   g_wo_hi);
    cudaGetSymbolAddress((void**)&wol,   g_wo_lo);
    cudaGetSymbolAddress((void**)&w1h,   g_w1_hi);
    cudaGetSymbolAddress((void**)&w1l,   g_w1_lo);
    cudaGetSymbolAddress((void**)&w2h,   g_w2_hi);
    cudaGetSymbolAddress((void**)&w2l,   g_w2_lo);

    const int SM128 = 2*(2*16384 + 2*128*128);   /* 131072 */
    const int SM256 = 2*(2*16384 + 2*256*128);   /* 196608 */
    cudaFuncSetAttribute(gemm_mma<128>, cudaFuncAttributeMaxDynamicSharedMemorySize, SM128);
    cudaFuncSetAttribute(gemm_mma<256>, cudaFuncAttributeMaxDynamicSharedMemorySize, SM256);
    cudaFuncSetAttribute(attn_kernel,   cudaFuncAttributeMaxDynamicSharedMemorySize,
                         2 * KVT * HD * (int)sizeof(float));

    /* ---- weight split + packing ---- */
    {
        const int T = 256, V4 = 4 * T;
        int nD = DEPTH*DIM*DIM;        /* per-proj total */
        int nH = DEPTH*HIDDEN*DIM;
        /* QKV pack: [DEPTH][2304][768] */
        cvt_split_pack<<<(nD + V4-1)/V4, T>>>(wq,  wqkvh, wqkvl, nD, DIM*DIM, QS*DIM, 0);
        cvt_split_pack<<<(nD + V4-1)/V4, T>>>(wk,  wqkvh, wqkvl, nD, DIM*DIM, QS*DIM, DIM*DIM);
        cvt_split_pack<<<(nD + V4-1)/V4, T>>>(wv,  wqkvh, wqkvl, nD, DIM*DIM, QS*DIM, 2*DIM*DIM);
        /* WO plain */
        cvt_split_pack<<<(nD + V4-1)/V4, T>>>(wo,  woh, wol, nD, DIM*DIM, DIM*DIM, 0);
        /* W1 pack: [DEPTH][4096][768] */
        cvt_split_pack<<<(nH + V4-1)/V4, T>>>(w1g, w1h, w1l, nH, HIDDEN*DIM, GUS*DIM, 0);
        cvt_split_pack<<<(nH + V4-1)/V4, T>>>(w1x, w1h, w1l, nH, HIDDEN*DIM, GUS*DIM, HIDDEN*DIM);
        /* W2 plain */
        cvt_split_pack<<<(nH + V4-1)/V4, T>>>(w2,  w2h, w2l, nH, DIM*HIDDEN, DIM*HIDDEN, 0);
        pack_bias_qkv<<<(DEPTH*QS + 255)/256, 256>>>(bq, bv, bqkv);
        pack_bias_mlp<<<(DEPTH*GUS + 255)/256, 256>>>(b1g, b1x, b1);
    }

    add_pos_kernel<<<(TOKENS*DIM + 255)/256, 256>>>(x, pos, h);

    dim3 gQKV(QS/256,    TOKENS/128);   /* (9, 32)  */
    dim3 gMLP(GUS/256,   TOKENS/128);   /* (16, 32) */
    dim3 gO  (DIM/128,   TOKENS/128);   /* (6, 32)  */

    for (int l = 0; l < DEPTH; l++) {
        size_t oqkv = (size_t)l * QS * DIM;
        size_t owo  = (size_t)l * DIM * DIM;
        size_t ow1  = (size_t)l * GUS * DIM;
        size_t ow2  = (size_t)l * DIM * HIDDEN;

        /* ---- attention ---- */
        ln_kernel<<<TOKENS, 256>>>(h, ln1_w + l*DIM, ln1_b + l*DIM, yhh, yhl, DIM);
        gemm_mma<256><<<gQKV, 512, SM256>>>(yhh, yhl, wqkvh + oqkv, wqkvl + oqkv,
                                            bqkv + l*QS, nullptr, qkv, TOKENS, QS, DIM);
        rope_kernel<<<(TOKENS*(DIM/2) + 255)/256, 256>>>(qkv, rope);
        attn_kernel<<<BATCH*HEADS*2, 256, 2*KVT*HD*sizeof(float)>>>(qkv, ohh, ohl);
        gemm_mma<128><<<gO, 256, SM128>>>(ohh, ohl, woh + owo, wol + owo,
                                          bo + l*DIM, h, h, TOKENS, DIM, DIM);

        /* ---- SwiGLU MLP ---- */
        ln_kernel<<<TOKENS, 256>>>(h, ln2_w + l*DIM, ln2_b + l*DIM, yhh, yhl, DIM);
        gemm_mma<256><<<gMLP, 512, SM256>>>(yhh, yhl, w1h + ow1, w1l + ow1,
                                            b1 + l*GUS, nullptr, gu, TOKENS, GUS, DIM);
        mlp_act_ln_kernel<<<TOKENS, 256>>>(gu, lnm_w + l*HIDDEN, lnm_b + l*HIDDEN, mhh, mhl);
        gemm_mma<128><<<gO, 256, SM128>>>(mhh, mhl, w2h + ow2, w2l + ow2,
                                          b2 + l*DIM, h, h, TOKENS, DIM, HIDDEN);
    }
}